// round 1
// baseline (speedup 1.0000x reference)
#include <cuda_runtime.h>

#define FULLMASK 0xffffffffu

constexpr int D        = 128;   // embedding dim
constexpr int K        = 64;    // categorical dim
constexpr int BM       = 64;    // batch rows per block
constexpr int NTHREADS = 256;
constexpr int NNEG     = 5;
constexpr int MAXBLOCKS = 4096;

// per-block loss partials (deterministic two-stage reduction, no atomics)
__device__ float g_partials[MAXBLOCKS];

// dynamic smem layout (floats):
//   [0, 16384)        sPW  : (prod, w_e) interleaved pairs, layout [d][b][2]
//   [16384, 24576)    sWcm : community_w transposed+swizzled, [d][k^((d&15)<<2)]
constexpr int SPW_FLOATS  = D * BM * 2;                     // 16384
constexpr int SWCM_FLOATS = D * K;                          // 8192
constexpr int SMEM_BYTES  = (SPW_FLOATS + SWCM_FLOATS) * 4; // 98304

// ---------------- packed f32x2 helpers (PTX-only on Blackwell) ----------------
__device__ __forceinline__ unsigned long long fma2(unsigned long long a,
                                                   unsigned long long b,
                                                   unsigned long long c) {
    unsigned long long r;
    asm("fma.rn.f32x2 %0, %1, %2, %3;" : "=l"(r) : "l"(a), "l"(b), "l"(c));
    return r;
}
__device__ __forceinline__ unsigned long long dup2(float x) {
    unsigned long long r;
    asm("mov.b64 %0, {%1, %2};" : "=l"(r) : "f"(x), "f"(x));
    return r;
}
__device__ __forceinline__ float2 unpk(unsigned long long v) {
    float2 f;
    asm("mov.b64 {%0, %1}, %2;" : "=f"(f.x), "=f"(f.y) : "l"(v));
    return f;
}

// ---------------- warp reduction helpers ----------------
__device__ __forceinline__ float wsum(float v) {
    #pragma unroll
    for (int o = 16; o > 0; o >>= 1) v += __shfl_xor_sync(FULLMASK, v, o);
    return v;
}
__device__ __forceinline__ float wmax(float v) {
    #pragma unroll
    for (int o = 16; o > 0; o >>= 1) v = fmaxf(v, __shfl_xor_sync(FULLMASK, v, o));
    return v;
}

__device__ __forceinline__ float dot4(float4 a, float4 b) {
    return fmaf(a.x, b.x, fmaf(a.y, b.y, fmaf(a.z, b.z, a.w * b.w)));
}

// log_sigmoid(x) = min(x,0) - log1p(exp(-|x|))
__device__ __forceinline__ float log_sigmoid(float x) {
    float e = __expf(-fabsf(x));
    return fminf(x, 0.0f) - log1pf(e);
}

// =============================================================================
// Fused kernel: gather + (q,prior) GEMM (f32x2) + softmax + argmax + loss dots
// =============================================================================
__global__ __launch_bounds__(NTHREADS, 2)
void gcn_gumbel_mega(const int*   __restrict__ widx,
                     const int*   __restrict__ cidx,
                     const int*   __restrict__ negidx,
                     const float* __restrict__ gumbel,
                     const float* __restrict__ node_emb,
                     const float* __restrict__ ctx_emb,
                     const float* __restrict__ Wg,       // community_w [K][D] row-major
                     float*       __restrict__ outq,     // softmax(q)  [B][K]
                     float*       __restrict__ outp,     // prior       [B][K]
                     int Btot)
{
    extern __shared__ float smem[];
    float* sPW  = smem;                 // [d][b][2] (prod, w_e)
    float* sWcm = smem + SPW_FLOATS;    // [d][k swizzled]

    __shared__ int   skstar[BM];
    __shared__ float sred[8];

    const int tid  = threadIdx.x;
    const int lane = tid & 31;
    const int warp = tid >> 5;
    const int b0   = blockIdx.x * BM;

    // ---------------- Phase 1: stage W (swizzled transpose) + gathers ----------------
    // W: read coalesced rows, store transposed with XOR swizzle (2-way conflict only)
    for (int i = tid; i < K * D; i += NTHREADS) {
        int k = i >> 7;          // row of community_w
        int d = i & (D - 1);
        sWcm[d * K + (k ^ ((d & 15) << 2))] = Wg[i];
    }

    // embeddings: 4 threads per batch row, each covers 32 floats
    {
        int r       = tid >> 2;        // 0..63 local row
        int quarter = tid & 3;         // 0..3
        int b       = b0 + r;
        int bsafe   = min(b, Btot - 1);
        int wi = widx[bsafe];
        int ci = cidx[bsafe];
        const float4* wp = (const float4*)(node_emb + (size_t)wi * D + quarter * 32);
        const float4* cp = (const float4*)(node_emb + (size_t)ci * D + quarter * 32);
        float2* dst = (float2*)sPW;    // pair index = d*BM + r
        #pragma unroll
        for (int j = 0; j < 8; j++) {
            float4 a  = wp[j];
            float4 bb = cp[j];
            int dbase = quarter * 32 + j * 4;
            dst[(dbase + 0) * BM + r] = make_float2(a.x * bb.x, a.x);
            dst[(dbase + 1) * BM + r] = make_float2(a.y * bb.y, a.y);
            dst[(dbase + 2) * BM + r] = make_float2(a.z * bb.z, a.z);
            dst[(dbase + 3) * BM + r] = make_float2(a.w * bb.w, a.w);
        }
    }
    __syncthreads();

    // ---------------- Phase 2: dual GEMM via packed f32x2 ----------------
    // thread tile: 4 batch rows x 4 k columns; acc packs (q, prior) per output
    const int tx = tid & 15;       // k-group
    const int ty = tid >> 4;       // b-group (16 groups x 4 rows)
    const int kb = tx * 4;
    const int bb = ty * 4;

    unsigned long long acc[4][4];
    #pragma unroll
    for (int i = 0; i < 4; i++)
        #pragma unroll
        for (int j = 0; j < 4; j++) acc[i][j] = 0ull;

    #pragma unroll 4
    for (int d = 0; d < D; d++) {
        const float4 wv = *(const float4*)&sWcm[d * K + (kb ^ ((d & 15) << 2))];
        unsigned long long w0 = dup2(wv.x);
        unsigned long long w1 = dup2(wv.y);
        unsigned long long w2 = dup2(wv.z);
        unsigned long long w3 = dup2(wv.w);
        const unsigned long long* pw =
            (const unsigned long long*)(sPW + (size_t)(d * BM + bb) * 2);
        unsigned long long a0 = pw[0];
        unsigned long long a1 = pw[1];
        unsigned long long a2 = pw[2];
        unsigned long long a3 = pw[3];
        acc[0][0] = fma2(a0, w0, acc[0][0]);
        acc[0][1] = fma2(a0, w1, acc[0][1]);
        acc[0][2] = fma2(a0, w2, acc[0][2]);
        acc[0][3] = fma2(a0, w3, acc[0][3]);
        acc[1][0] = fma2(a1, w0, acc[1][0]);
        acc[1][1] = fma2(a1, w1, acc[1][1]);
        acc[1][2] = fma2(a1, w2, acc[1][2]);
        acc[1][3] = fma2(a1, w3, acc[1][3]);
        acc[2][0] = fma2(a2, w0, acc[2][0]);
        acc[2][1] = fma2(a2, w1, acc[2][1]);
        acc[2][2] = fma2(a2, w2, acc[2][2]);
        acc[2][3] = fma2(a2, w3, acc[2][3]);
        acc[3][0] = fma2(a3, w0, acc[3][0]);
        acc[3][1] = fma2(a3, w1, acc[3][1]);
        acc[3][2] = fma2(a3, w2, acc[3][2]);
        acc[3][3] = fma2(a3, w3, acc[3][3]);
    }
    __syncthreads();   // all phase-2 reads of sPW done before reuse

    // ---------------- Phase 3: dump q / prior logits to smem ----------------
    float* sQ = smem;            // [BM][K]
    float* sP = smem + BM * K;   // [BM][K]
    #pragma unroll
    for (int i = 0; i < 4; i++) {
        #pragma unroll
        for (int j = 0; j < 4; j++) {
            float2 qp = unpk(acc[i][j]);
            sQ[(bb + i) * K + (kb + j)] = qp.x;
            sP[(bb + i) * K + (kb + j)] = qp.y;
        }
    }
    __syncthreads();

    // ---------------- Phase 4: softmax(q), softmax(prior), argmax(q+g) ----------------
    for (int r = warp; r < BM; r += 8) {
        int b = b0 + r;
        if (b >= Btot) continue;

        float q1 = sQ[r * K + lane];
        float q2 = sQ[r * K + 32 + lane];
        float g1 = gumbel[(size_t)b * K + lane];
        float g2 = gumbel[(size_t)b * K + 32 + lane];

        // softmax(q)
        float mq  = wmax(fmaxf(q1, q2));
        float e1  = __expf(q1 - mq);
        float e2  = __expf(q2 - mq);
        float inv = __fdividef(1.0f, wsum(e1 + e2));
        outq[(size_t)b * K + lane]      = e1 * inv;
        outq[(size_t)b * K + 32 + lane] = e2 * inv;

        // argmax(q + gumbel)  (first-max tie semantics)
        float av = q1 + g1;
        int   ai = lane;
        {
            float a2v = q2 + g2;
            if (a2v > av) { av = a2v; ai = lane + 32; }
        }
        #pragma unroll
        for (int o = 16; o > 0; o >>= 1) {
            float ov = __shfl_xor_sync(FULLMASK, av, o);
            int   oi = __shfl_xor_sync(FULLMASK, ai, o);
            if (ov > av || (ov == av && oi < ai)) { av = ov; ai = oi; }
        }
        if (lane == 0) skstar[r] = ai;

        // softmax(prior logits)
        float p1 = sP[r * K + lane];
        float p2 = sP[r * K + 32 + lane];
        float mp = wmax(fmaxf(p1, p2));
        float f1 = __expf(p1 - mp);
        float f2 = __expf(p2 - mp);
        float ip = __fdividef(1.0f, wsum(f1 + f2));
        outp[(size_t)b * K + lane]      = f1 * ip;
        outp[(size_t)b * K + 32 + lane] = f2 * ip;
    }
    __syncthreads();

    // ---------------- Phase 5: loss dots with W[k*] ----------------
    float lacc = 0.0f;
    for (int r = warp; r < BM; r += 8) {
        int b = b0 + r;
        if (b >= Btot) continue;

        int kst = skstar[r];
        // W row from global (32KB table -> L1 resident), coalesced float4
        float4 wv = *(const float4*)(Wg + (size_t)kst * D + lane * 4);

        int ci = cidx[b];
        float4 cv = *(const float4*)(ctx_emb + (size_t)ci * D + lane * 4);

        int nidx[NNEG];
        #pragma unroll
        for (int j = 0; j < NNEG; j++) nidx[j] = negidx[(size_t)b * NNEG + j];
        float4 nv[NNEG];
        #pragma unroll
        for (int j = 0; j < NNEG; j++)
            nv[j] = *(const float4*)(ctx_emb + (size_t)nidx[j] * D + lane * 4);

        float s[NNEG + 1];
        s[0] = dot4(wv, cv);
        #pragma unroll
        for (int j = 0; j < NNEG; j++) s[j + 1] = dot4(wv, nv[j]);
        #pragma unroll
        for (int t = 0; t < NNEG + 1; t++) s[t] = wsum(s[t]);

        float term = log_sigmoid(s[0]);
        float nsum = 0.0f;
        #pragma unroll
        for (int j = 0; j < NNEG; j++) nsum += log_sigmoid(-s[j + 1]);
        term = fmaf(nsum, 1.0f / (float)NNEG, term);

        if (lane == 0) lacc += term;
    }

    if (lane == 0) sred[warp] = lacc;
    __syncthreads();
    if (tid == 0) {
        float s = 0.0f;
        #pragma unroll
        for (int i = 0; i < 8; i++) s += sred[i];
        g_partials[blockIdx.x] = s;
    }
}

// =============================================================================
// Deterministic final loss reduction
// =============================================================================
__global__ void gcn_finalize(int nblocks, float* __restrict__ out0, float invB)
{
    __shared__ float sr[256];
    float s = 0.0f;
    for (int i = threadIdx.x; i < nblocks; i += 256) s += g_partials[i];
    sr[threadIdx.x] = s;
    __syncthreads();
    #pragma unroll
    for (int o = 128; o > 0; o >>= 1) {
        if (threadIdx.x < o) sr[threadIdx.x] += sr[threadIdx.x + o];
        __syncthreads();
    }
    if (threadIdx.x == 0) out0[0] = -sr[0] * invB;
}

// =============================================================================
// Launch
// =============================================================================
extern "C" void kernel_launch(void* const* d_in, const int* in_sizes, int n_in,
                              void* d_out, int out_size)
{
    const int*   w        = (const int*)  d_in[0];
    const int*   c        = (const int*)  d_in[1];
    const int*   neg      = (const int*)  d_in[2];
    // d_in[3] = temp (==1): only rescales the argmax input -> provably irrelevant
    const float* gumbel   = (const float*)d_in[4];
    const float* node_emb = (const float*)d_in[5];
    const float* ctx_emb  = (const float*)d_in[6];
    const float* Wg       = (const float*)d_in[7];

    const int B = in_sizes[0];

    float* out       = (float*)d_out;
    float* out_q     = out + 1;
    float* out_prior = out + 1 + (size_t)B * K;

    int nb = (B + BM - 1) / BM;     // 2048 for B=131072
    if (nb > MAXBLOCKS) nb = MAXBLOCKS;   // (B fixed at 131072; guard only)

    cudaFuncSetAttribute(gcn_gumbel_mega,
                         cudaFuncAttributeMaxDynamicSharedMemorySize, SMEM_BYTES);

    gcn_gumbel_mega<<<nb, NTHREADS, SMEM_BYTES>>>(
        w, c, neg, gumbel, node_emb, ctx_emb, Wg, out_q, out_prior, B);

    gcn_finalize<<<1, 256>>>(nb, out, 1.0f / (float)B);
}

// round 2
// speedup vs baseline: 1.0744x; 1.0744x over previous
#include <cuda_runtime.h>

#define FULLMASK 0xffffffffu

constexpr int D        = 128;   // embedding dim
constexpr int K        = 64;    // categorical dim
constexpr int BM       = 64;    // batch rows per block
constexpr int NTHREADS = 256;
constexpr int NNEG     = 5;
constexpr int MAXBLOCKS = 4096;

// per-block loss partials + completion counter (deterministic last-block reduce)
__device__ float        g_partials[MAXBLOCKS];
__device__ unsigned int g_counter = 0;

// dynamic smem layout (floats):
//   [0, 16384)        sPW  : (prod, w_e) interleaved pairs, layout [d][b][2]
//                     (later overlaid by sQ [BM][K] and sP [BM][K])
//   [16384, 24576)    sWcm : community_w transposed+swizzled
constexpr int SPW_FLOATS  = D * BM * 2;                     // 16384
constexpr int SWCM_FLOATS = D * K;                          // 8192
constexpr int SMEM_BYTES  = (SPW_FLOATS + SWCM_FLOATS) * 4; // 98304

// ---------------- packed f32x2 helpers (PTX-only on Blackwell) ----------------
__device__ __forceinline__ unsigned long long fma2(unsigned long long a,
                                                   unsigned long long b,
                                                   unsigned long long c) {
    unsigned long long r;
    asm("fma.rn.f32x2 %0, %1, %2, %3;" : "=l"(r) : "l"(a), "l"(b), "l"(c));
    return r;
}
__device__ __forceinline__ unsigned long long dup2(float x) {
    unsigned long long r;
    asm("mov.b64 %0, {%1, %2};" : "=l"(r) : "f"(x), "f"(x));
    return r;
}
__device__ __forceinline__ float2 unpk(unsigned long long v) {
    float2 f;
    asm("mov.b64 {%0, %1}, %2;" : "=f"(f.x), "=f"(f.y) : "l"(v));
    return f;
}

// ---------------- warp reduction helpers ----------------
__device__ __forceinline__ float wsum(float v) {
    #pragma unroll
    for (int o = 16; o > 0; o >>= 1) v += __shfl_xor_sync(FULLMASK, v, o);
    return v;
}
__device__ __forceinline__ float wmax(float v) {
    #pragma unroll
    for (int o = 16; o > 0; o >>= 1) v = fmaxf(v, __shfl_xor_sync(FULLMASK, v, o));
    return v;
}

__device__ __forceinline__ float dot4(float4 a, float4 b) {
    return fmaf(a.x, b.x, fmaf(a.y, b.y, fmaf(a.z, b.z, a.w * b.w)));
}

// log_sigmoid(x) = min(x,0) - log(1 + exp(-|x|))
__device__ __forceinline__ float log_sigmoid(float x) {
    float e = __expf(-fabsf(x));
    return fminf(x, 0.0f) - __logf(1.0f + e);
}

// =============================================================================
// Single fused kernel: gather + dual GEMM (f32x2) + softmax/argmax + loss +
// deterministic cross-block loss reduction (last block).
// =============================================================================
__global__ __launch_bounds__(NTHREADS, 2)
void gcn_gumbel_mega(const int*   __restrict__ widx,
                     const int*   __restrict__ cidx,
                     const int*   __restrict__ negidx,
                     const float* __restrict__ gumbel,
                     const float* __restrict__ node_emb,
                     const float* __restrict__ ctx_emb,
                     const float* __restrict__ Wg,       // community_w [K][D]
                     float*       __restrict__ out0,     // loss scalar
                     float*       __restrict__ outq,     // softmax(q)  [B][K]
                     float*       __restrict__ outp,     // prior       [B][K]
                     int Btot, float invB)
{
    extern __shared__ float smem[];
    float* sPW  = smem;                 // [d][b][2] (prod, w_e)
    float* sWcm = smem + SPW_FLOATS;    // [d][k swizzled]

    __shared__ float sred[8];
    __shared__ int   s_last;

    const int tid  = threadIdx.x;
    const int lane = tid & 31;
    const int warp = tid >> 5;
    const int b0   = blockIdx.x * BM;

    // ---------------- Phase 0: gumbel prefetch (streaming, evict-first) --------
    // Warp owns rows warp*8 .. warp*8+7 for phases 4/5; prefetch its gumbel now
    // so the DRAM latency hides behind phases 1-3.
    float gg1[8], gg2[8];
    {
        const int rbase = warp * 8;
        #pragma unroll
        for (int j = 0; j < 8; j++) {
            int b = min(b0 + rbase + j, Btot - 1);
            gg1[j] = __ldcs(gumbel + (size_t)b * K + lane);
            gg2[j] = __ldcs(gumbel + (size_t)b * K + 32 + lane);
        }
    }

    // ---------------- Phase 1: embedding gathers + W staging ----------------
    {
        int r       = tid >> 2;        // 0..63 local row
        int quarter = tid & 3;         // 0..3
        int b       = min(b0 + r, Btot - 1);
        int wi = widx[b];
        int ci = cidx[b];
        const float4* wp = (const float4*)(node_emb + (size_t)wi * D + quarter * 32);
        const float4* cp = (const float4*)(node_emb + (size_t)ci * D + quarter * 32);
        float2* dst = (float2*)sPW;    // pair index = d*BM + r
        #pragma unroll
        for (int j = 0; j < 8; j++) {
            float4 a  = wp[j];
            float4 bb = cp[j];
            int dbase = quarter * 32 + j * 4;
            dst[(dbase + 0) * BM + r] = make_float2(a.x * bb.x, a.x);
            dst[(dbase + 1) * BM + r] = make_float2(a.y * bb.y, a.y);
            dst[(dbase + 2) * BM + r] = make_float2(a.z * bb.z, a.z);
            dst[(dbase + 3) * BM + r] = make_float2(a.w * bb.w, a.w);
        }
    }
    // W: coalesced LDG.128, store transposed with XOR swizzle
    {
        const float4* W4 = (const float4*)Wg;
        #pragma unroll
        for (int it = 0; it < (K * D / 4) / NTHREADS; it++) {
            int i = tid + it * NTHREADS;
            float4 v  = W4[i];
            int base  = i * 4;
            int k     = base >> 7;          // row of community_w
            int d0    = base & (D - 1);
            sWcm[(d0 + 0) * K + (k ^ (((d0 + 0) & 15) << 2))] = v.x;
            sWcm[(d0 + 1) * K + (k ^ (((d0 + 1) & 15) << 2))] = v.y;
            sWcm[(d0 + 2) * K + (k ^ (((d0 + 2) & 15) << 2))] = v.z;
            sWcm[(d0 + 3) * K + (k ^ (((d0 + 3) & 15) << 2))] = v.w;
        }
    }
    __syncthreads();

    // ---------------- Phase 2: dual GEMM via packed f32x2 ----------------
    const int tx = tid & 15;       // k-group
    const int ty = tid >> 4;       // b-group
    const int kb = tx * 4;
    const int bb = ty * 4;

    unsigned long long acc[4][4];
    #pragma unroll
    for (int i = 0; i < 4; i++)
        #pragma unroll
        for (int j = 0; j < 4; j++) acc[i][j] = 0ull;

    #pragma unroll 4
    for (int d = 0; d < D; d++) {
        const float4 wv = *(const float4*)&sWcm[d * K + (kb ^ ((d & 15) << 2))];
        unsigned long long w0 = dup2(wv.x);
        unsigned long long w1 = dup2(wv.y);
        unsigned long long w2 = dup2(wv.z);
        unsigned long long w3 = dup2(wv.w);
        const unsigned long long* pw =
            (const unsigned long long*)(sPW + (size_t)(d * BM + bb) * 2);
        unsigned long long a0 = pw[0];
        unsigned long long a1 = pw[1];
        unsigned long long a2 = pw[2];
        unsigned long long a3 = pw[3];
        acc[0][0] = fma2(a0, w0, acc[0][0]);
        acc[0][1] = fma2(a0, w1, acc[0][1]);
        acc[0][2] = fma2(a0, w2, acc[0][2]);
        acc[0][3] = fma2(a0, w3, acc[0][3]);
        acc[1][0] = fma2(a1, w0, acc[1][0]);
        acc[1][1] = fma2(a1, w1, acc[1][1]);
        acc[1][2] = fma2(a1, w2, acc[1][2]);
        acc[1][3] = fma2(a1, w3, acc[1][3]);
        acc[2][0] = fma2(a2, w0, acc[2][0]);
        acc[2][1] = fma2(a2, w1, acc[2][1]);
        acc[2][2] = fma2(a2, w2, acc[2][2]);
        acc[2][3] = fma2(a2, w3, acc[2][3]);
        acc[3][0] = fma2(a3, w0, acc[3][0]);
        acc[3][1] = fma2(a3, w1, acc[3][1]);
        acc[3][2] = fma2(a3, w2, acc[3][2]);
        acc[3][3] = fma2(a3, w3, acc[3][3]);
    }
    __syncthreads();   // all phase-2 reads of sPW done before overlay

    // ---------------- Phase 3: dump q / prior logits (vectorized) -------------
    float* sQ = smem;            // [BM][K]
    float* sP = smem + BM * K;   // [BM][K]
    #pragma unroll
    for (int i = 0; i < 4; i++) {
        float2 t0 = unpk(acc[i][0]);
        float2 t1 = unpk(acc[i][1]);
        float2 t2 = unpk(acc[i][2]);
        float2 t3 = unpk(acc[i][3]);
        *(float4*)&sQ[(bb + i) * K + kb] = make_float4(t0.x, t1.x, t2.x, t3.x);
        *(float4*)&sP[(bb + i) * K + kb] = make_float4(t0.y, t1.y, t2.y, t3.y);
    }
    __syncthreads();

    // ---------------- Phase 4+5: per-warp rows (no cross-warp sync) -----------
    float lacc = 0.0f;
    #pragma unroll 2
    for (int j = 0; j < 8; j++) {
        int r = warp * 8 + j;
        int b = b0 + r;
        if (b >= Btot) break;

        // issue index + context gathers first (latency overlap with shfl trees)
        int ci = cidx[b];
        int nix[NNEG];
        #pragma unroll
        for (int t = 0; t < NNEG; t++) nix[t] = negidx[(size_t)b * NNEG + t];
        float4 cv = *(const float4*)(ctx_emb + (size_t)ci * D + (lane << 2));
        float4 nv[NNEG];
        #pragma unroll
        for (int t = 0; t < NNEG; t++)
            nv[t] = *(const float4*)(ctx_emb + (size_t)nix[t] * D + (lane << 2));

        float q1 = sQ[r * K + lane];
        float q2 = sQ[r * K + 32 + lane];
        float p1 = sP[r * K + lane];
        float p2 = sP[r * K + 32 + lane];

        // softmax(q)
        float mq  = wmax(fmaxf(q1, q2));
        float e1  = __expf(q1 - mq);
        float e2  = __expf(q2 - mq);
        float inv = __fdividef(1.0f, wsum(e1 + e2));
        __stcs(outq + (size_t)b * K + lane,      e1 * inv);
        __stcs(outq + (size_t)b * K + 32 + lane, e2 * inv);

        // argmax(q + gumbel): per-lane best, warp max, ballot leader
        float av = q1 + gg1[j];
        int   ai = lane;
        {
            float a2v = q2 + gg2[j];
            if (a2v > av) { av = a2v; ai = lane + 32; }
        }
        float    mv  = wmax(av);
        unsigned msk = __ballot_sync(FULLMASK, av == mv);
        int      kst = __shfl_sync(FULLMASK, ai, __ffs(msk) - 1);

        // softmax(prior logits)
        float mp = wmax(fmaxf(p1, p2));
        float f1 = __expf(p1 - mp);
        float f2 = __expf(p2 - mp);
        float ip = __fdividef(1.0f, wsum(f1 + f2));
        __stcs(outp + (size_t)b * K + lane,      f1 * ip);
        __stcs(outp + (size_t)b * K + 32 + lane, f2 * ip);

        // loss dots with W[k*] (hot 32KB table -> L1)
        float4 wv = *(const float4*)(Wg + (size_t)kst * D + (lane << 2));
        float s0 = dot4(wv, cv);
        float s1 = dot4(wv, nv[0]);
        float s2 = dot4(wv, nv[1]);
        float s3 = dot4(wv, nv[2]);
        float s4 = dot4(wv, nv[3]);
        float s5 = dot4(wv, nv[4]);
        s0 = wsum(s0); s1 = wsum(s1); s2 = wsum(s2);
        s3 = wsum(s3); s4 = wsum(s4); s5 = wsum(s5);

        float term = log_sigmoid(s0);
        float nsum = log_sigmoid(-s1) + log_sigmoid(-s2) + log_sigmoid(-s3)
                   + log_sigmoid(-s4) + log_sigmoid(-s5);
        term = fmaf(nsum, 1.0f / (float)NNEG, term);
        if (lane == 0) lacc += term;
    }

    // ---------------- Block partial + last-block deterministic reduce ---------
    if (lane == 0) sred[warp] = lacc;
    __syncthreads();
    if (tid == 0) {
        float s = 0.0f;
        #pragma unroll
        for (int i = 0; i < 8; i++) s += sred[i];
        g_partials[blockIdx.x] = s;
        __threadfence();
        unsigned t = atomicAdd(&g_counter, 1u);
        s_last = (t == gridDim.x - 1) ? 1 : 0;
    }
    __syncthreads();

    if (s_last) {
        float s = 0.0f;
        for (int i = tid; i < (int)gridDim.x; i += NTHREADS)
            s += __ldcg(&g_partials[i]);
        smem[tid] = s;
        __syncthreads();
        #pragma unroll
        for (int o = NTHREADS / 2; o > 0; o >>= 1) {
            if (tid < o) smem[tid] += smem[tid + o];
            __syncthreads();
        }
        if (tid == 0) {
            out0[0] = -smem[0] * invB;
            g_counter = 0;   // reset for next (graph-replayed) launch
        }
    }
}

// =============================================================================
// Launch (single kernel per call -> ncu -s 5 -c 1 lands on the mega kernel)
// =============================================================================
extern "C" void kernel_launch(void* const* d_in, const int* in_sizes, int n_in,
                              void* d_out, int out_size)
{
    const int*   w        = (const int*)  d_in[0];
    const int*   c        = (const int*)  d_in[1];
    const int*   neg      = (const int*)  d_in[2];
    // d_in[3] = temp (==1): only rescales the argmax input -> provably irrelevant
    const float* gumbel   = (const float*)d_in[4];
    const float* node_emb = (const float*)d_in[5];
    const float* ctx_emb  = (const float*)d_in[6];
    const float* Wg       = (const float*)d_in[7];

    const int B = in_sizes[0];

    float* out       = (float*)d_out;
    float* out_q     = out + 1;
    float* out_prior = out + 1 + (size_t)B * K;

    int nb = (B + BM - 1) / BM;     // 2048 for B=131072
    if (nb > MAXBLOCKS) nb = MAXBLOCKS;

    cudaFuncSetAttribute(gcn_gumbel_mega,
                         cudaFuncAttributeMaxDynamicSharedMemorySize, SMEM_BYTES);

    gcn_gumbel_mega<<<nb, NTHREADS, SMEM_BYTES>>>(
        w, c, neg, gumbel, node_emb, ctx_emb, Wg,
        out, out_q, out_prior, B, 1.0f / (float)B);
}

// round 5
// speedup vs baseline: 1.2385x; 1.1527x over previous
#include <cuda_runtime.h>
#include <cstdint>

#define FULLMASK 0xffffffffu

constexpr int D        = 128;   // embedding dim
constexpr int K        = 64;    // categorical dim
constexpr int BM       = 64;    // batch rows per block
constexpr int NTHREADS = 256;
constexpr int NNEG     = 5;
constexpr int MAXBLOCKS = 4096;

// device-global scratch (no allocs allowed)
__device__ float        g_WT[D * K];        // W transposed: [d][k], 32KB (L1-hot)
__device__ float        g_partials[MAXBLOCKS];
__device__ unsigned int g_counter = 0;

// dynamic smem: sPW [d][b][2] (prod, w_e) pairs = 64KB; phase-3 overlays sQ/sP.
constexpr int SPW_FLOATS = D * BM * 2;               // 16384
constexpr int SMEM_BYTES = SPW_FLOATS * 4;           // 65536 -> 3 blocks/SM

// ---------------- packed f32x2 helpers (PTX-only on Blackwell) ----------------
__device__ __forceinline__ unsigned long long fma2(unsigned long long a,
                                                   unsigned long long b,
                                                   unsigned long long c) {
    unsigned long long r;
    asm("fma.rn.f32x2 %0, %1, %2, %3;" : "=l"(r) : "l"(a), "l"(b), "l"(c));
    return r;
}
__device__ __forceinline__ unsigned long long dup2(float x) {
    unsigned long long r;
    asm("mov.b64 %0, {%1, %2};" : "=l"(r) : "f"(x), "f"(x));
    return r;
}
__device__ __forceinline__ float2 unpk(unsigned long long v) {
    float2 f;
    asm("mov.b64 {%0, %1}, %2;" : "=f"(f.x), "=f"(f.y) : "l"(v));
    return f;
}

__device__ __forceinline__ float wsum(float v) {
    #pragma unroll
    for (int o = 16; o > 0; o >>= 1) v += __shfl_xor_sync(FULLMASK, v, o);
    return v;
}
__device__ __forceinline__ float wmax(float v) {
    #pragma unroll
    for (int o = 16; o > 0; o >>= 1) v = fmaxf(v, __shfl_xor_sync(FULLMASK, v, o));
    return v;
}
__device__ __forceinline__ float dot4(float4 a, float4 b) {
    return fmaf(a.x, b.x, fmaf(a.y, b.y, fmaf(a.z, b.z, a.w * b.w)));
}
__device__ __forceinline__ float log_sigmoid(float x) {
    float e = __expf(-fabsf(x));
    return fminf(x, 0.0f) - __logf(1.0f + e);
}

// =============================================================================
// Tiny one-time kernel: transpose community_w into g_WT[d][k]
// =============================================================================
__global__ void gcn_wt_setup(const float* __restrict__ Wg)
{
    int i = blockIdx.x * blockDim.x + threadIdx.x;   // 2048 float4s
    if (i >= K * D / 4) return;
    float4 v = ((const float4*)Wg)[i];
    int k  = i >> 5;            // row of community_w (D/4 = 32 float4 per row)
    int d0 = (i & 31) << 2;
    g_WT[(d0 + 0) * K + k] = v.x;
    g_WT[(d0 + 1) * K + k] = v.y;
    g_WT[(d0 + 2) * K + k] = v.z;
    g_WT[(d0 + 3) * K + k] = v.w;
}

// =============================================================================
// Fused kernel: gather + dual GEMM (f32x2, W from L1-hot global) + softmax /
// argmax + loss + deterministic cross-block loss reduction.
// =============================================================================
__global__ __launch_bounds__(NTHREADS, 3)
void gcn_gumbel_mega(const int*   __restrict__ widx,
                     const int*   __restrict__ cidx,
                     const int*   __restrict__ negidx,
                     const float* __restrict__ gumbel,
                     const float* __restrict__ node_emb,
                     const float* __restrict__ ctx_emb,
                     const float* __restrict__ Wg,       // community_w [K][D]
                     float*       __restrict__ out0,     // loss scalar
                     float*       __restrict__ outq,     // softmax(q)  [B][K]
                     float*       __restrict__ outp,     // prior       [B][K]
                     int Btot, float invB)
{
    extern __shared__ float smem[];
    float* sPW = smem;                 // [d][b][2] (prod, w_e)

    __shared__ float sred[8];
    __shared__ int   s_last;

    const int tid  = threadIdx.x;
    const int lane = tid & 31;
    const int warp = tid >> 5;
    const int b0   = blockIdx.x * BM;

    // ---------------- Phase 1: embedding gathers -> smem pairs ----------------
    {
        int r       = tid >> 2;        // 0..63 local row
        int quarter = tid & 3;         // 0..3
        int b       = min(b0 + r, Btot - 1);
        int wi = widx[b];
        int ci = cidx[b];
        const float4* wp = (const float4*)(node_emb + (size_t)wi * D + quarter * 32);
        const float4* cp = (const float4*)(node_emb + (size_t)ci * D + quarter * 32);
        float2* dst = (float2*)sPW;    // pair index = d*BM + r
        #pragma unroll
        for (int j = 0; j < 8; j++) {
            float4 a  = wp[j];
            float4 bb = cp[j];
            int dbase = quarter * 32 + j * 4;
            dst[(dbase + 0) * BM + r] = make_float2(a.x * bb.x, a.x);
            dst[(dbase + 1) * BM + r] = make_float2(a.y * bb.y, a.y);
            dst[(dbase + 2) * BM + r] = make_float2(a.z * bb.z, a.z);
            dst[(dbase + 3) * BM + r] = make_float2(a.w * bb.w, a.w);
        }
    }
    __syncthreads();

    // ---------------- Phase 2: dual GEMM, W columns from L1-hot g_WT ----------
    const int tx = tid & 15;       // k-group (16 groups x 4 k)
    const int ty = tid >> 4;       // b-group (16 groups x 4 rows)
    const int kb = tx * 4;
    const int bb = ty * 4;

    unsigned long long acc[4][4];
    #pragma unroll
    for (int i = 0; i < 4; i++)
        #pragma unroll
        for (int j = 0; j < 4; j++) acc[i][j] = 0ull;

    const float4* WT4 = (const float4*)(g_WT + kb);   // stride K floats per d

    #pragma unroll 4
    for (int d = 0; d < D; d++) {
        const float4 wv = __ldg(WT4 + d * (K / 4) * 0 + (size_t)d * (K / 4));
        unsigned long long w0 = dup2(wv.x);
        unsigned long long w1 = dup2(wv.y);
        unsigned long long w2 = dup2(wv.z);
        unsigned long long w3 = dup2(wv.w);
        const unsigned long long* pw =
            (const unsigned long long*)(sPW + (size_t)(d * BM + bb) * 2);
        unsigned long long a0 = pw[0];
        unsigned long long a1 = pw[1];
        unsigned long long a2 = pw[2];
        unsigned long long a3 = pw[3];
        acc[0][0] = fma2(a0, w0, acc[0][0]);
        acc[0][1] = fma2(a0, w1, acc[0][1]);
        acc[0][2] = fma2(a0, w2, acc[0][2]);
        acc[0][3] = fma2(a0, w3, acc[0][3]);
        acc[1][0] = fma2(a1, w0, acc[1][0]);
        acc[1][1] = fma2(a1, w1, acc[1][1]);
        acc[1][2] = fma2(a1, w2, acc[1][2]);
        acc[1][3] = fma2(a1, w3, acc[1][3]);
        acc[2][0] = fma2(a2, w0, acc[2][0]);
        acc[2][1] = fma2(a2, w1, acc[2][1]);
        acc[2][2] = fma2(a2, w2, acc[2][2]);
        acc[2][3] = fma2(a2, w3, acc[2][3]);
        acc[3][0] = fma2(a3, w0, acc[3][0]);
        acc[3][1] = fma2(a3, w1, acc[3][1]);
        acc[3][2] = fma2(a3, w2, acc[3][2]);
        acc[3][3] = fma2(a3, w3, acc[3][3]);
    }
    __syncthreads();   // all phase-2 reads of sPW done before overlay

    // ---------------- Phase 3: dump q / prior logits (vectorized) -------------
    float* sQ = smem;            // [BM][K] = 16KB
    float* sP = smem + BM * K;   // [BM][K] = 16KB
    #pragma unroll
    for (int i = 0; i < 4; i++) {
        float2 t0 = unpk(acc[i][0]);
        float2 t1 = unpk(acc[i][1]);
        float2 t2 = unpk(acc[i][2]);
        float2 t3 = unpk(acc[i][3]);
        *(float4*)&sQ[(bb + i) * K + kb] = make_float4(t0.x, t1.x, t2.x, t3.x);
        *(float4*)&sP[(bb + i) * K + kb] = make_float4(t0.y, t1.y, t2.y, t3.y);
    }
    __syncthreads();

    // ---------------- Phase 4+5: per-warp rows (no cross-warp sync) -----------
    float lacc = 0.0f;
    for (int j = 0; j < 8; j++) {
        int r = warp * 8 + j;
        int b = b0 + r;
        if (b >= Btot) break;

        float q1 = sQ[r * K + lane];
        float q2 = sQ[r * K + 32 + lane];
        float p1 = sP[r * K + lane];
        float p2 = sP[r * K + 32 + lane];
        float g1 = __ldcs(gumbel + (size_t)b * K + lane);
        float g2 = __ldcs(gumbel + (size_t)b * K + 32 + lane);

        // softmax(q)
        float mq  = wmax(fmaxf(q1, q2));
        float e1  = __expf(q1 - mq);
        float e2  = __expf(q2 - mq);
        float inv = __fdividef(1.0f, wsum(e1 + e2));
        __stcs(outq + (size_t)b * K + lane,      e1 * inv);
        __stcs(outq + (size_t)b * K + 32 + lane, e2 * inv);

        // argmax(q + gumbel): per-lane best, warp max, ballot leader
        float av = q1 + g1;
        int   ai = lane;
        {
            float a2v = q2 + g2;
            if (a2v > av) { av = a2v; ai = lane + 32; }
        }
        float    mv  = wmax(av);
        unsigned msk = __ballot_sync(FULLMASK, av == mv);
        int      kst = __shfl_sync(FULLMASK, ai, __ffs(msk) - 1);

        // softmax(prior logits)
        float mp = wmax(fmaxf(p1, p2));
        float f1 = __expf(p1 - mp);
        float f2 = __expf(p2 - mp);
        float ip = __fdividef(1.0f, wsum(f1 + f2));
        __stcs(outp + (size_t)b * K + lane,      f1 * ip);
        __stcs(outp + (size_t)b * K + 32 + lane, f2 * ip);

        // loss dots with W[k*] (hot 32KB table -> L1)
        int ci = cidx[b];
        float4 wv = *(const float4*)(Wg + (size_t)kst * D + (lane << 2));
        float4 cv = *(const float4*)(ctx_emb + (size_t)ci * D + (lane << 2));
        float s0 = dot4(wv, cv);
        float s1, s2, s3, s4, s5;
        {
            int n0 = negidx[(size_t)b * NNEG + 0];
            int n1 = negidx[(size_t)b * NNEG + 1];
            int n2 = negidx[(size_t)b * NNEG + 2];
            int n3 = negidx[(size_t)b * NNEG + 3];
            int n4 = negidx[(size_t)b * NNEG + 4];
            float4 v0 = *(const float4*)(ctx_emb + (size_t)n0 * D + (lane << 2));
            float4 v1 = *(const float4*)(ctx_emb + (size_t)n1 * D + (lane << 2));
            float4 v2 = *(const float4*)(ctx_emb + (size_t)n2 * D + (lane << 2));
            float4 v3 = *(const float4*)(ctx_emb + (size_t)n3 * D + (lane << 2));
            float4 v4 = *(const float4*)(ctx_emb + (size_t)n4 * D + (lane << 2));
            s1 = dot4(wv, v0);
            s2 = dot4(wv, v1);
            s3 = dot4(wv, v2);
            s4 = dot4(wv, v3);
            s5 = dot4(wv, v4);
        }
        s0 = wsum(s0); s1 = wsum(s1); s2 = wsum(s2);
        s3 = wsum(s3); s4 = wsum(s4); s5 = wsum(s5);

        float term = log_sigmoid(s0);
        float nsum = log_sigmoid(-s1) + log_sigmoid(-s2) + log_sigmoid(-s3)
                   + log_sigmoid(-s4) + log_sigmoid(-s5);
        term = fmaf(nsum, 1.0f / (float)NNEG, term);
        if (lane == 0) lacc += term;
    }

    // ---------------- Block partial + last-block deterministic reduce ---------
    if (lane == 0) sred[warp] = lacc;
    __syncthreads();
    if (tid == 0) {
        float s = 0.0f;
        #pragma unroll
        for (int i = 0; i < 8; i++) s += sred[i];
        g_partials[blockIdx.x] = s;
        __threadfence();
        unsigned t = atomicAdd(&g_counter, 1u);
        s_last = (t == gridDim.x - 1) ? 1 : 0;
    }
    __syncthreads();

    if (s_last) {
        float s = 0.0f;
        for (int i = tid; i < (int)gridDim.x; i += NTHREADS)
            s += __ldcg(&g_partials[i]);
        smem[tid] = s;
        __syncthreads();
        #pragma unroll
        for (int o = NTHREADS / 2; o > 0; o >>= 1) {
            if (tid < o) smem[tid] += smem[tid + o];
            __syncthreads();
        }
        if (tid == 0) {
            out0[0] = -smem[0] * invB;
            g_counter = 0;   // reset for next (graph-replayed) launch
        }
    }
}

// =============================================================================
extern "C" void kernel_launch(void* const* d_in, const int* in_sizes, int n_in,
                              void* d_out, int out_size)
{
    const int*   w        = (const int*)  d_in[0];
    const int*   c        = (const int*)  d_in[1];
    const int*   neg      = (const int*)  d_in[2];
    // d_in[3] = temp (==1): only rescales the argmax input -> provably irrelevant
    const float* gumbel   = (const float*)d_in[4];
    const float* node_emb = (const float*)d_in[5];
    const float* ctx_emb  = (const float*)d_in[6];
    const float* Wg       = (const float*)d_in[7];

    const int B = in_sizes[0];

    float* out       = (float*)d_out;
    float* out_q     = out + 1;
    float* out_prior = out + 1 + (size_t)B * K;

    int nb = (B + BM - 1) / BM;     // 2048 for B=131072
    if (nb > MAXBLOCKS) nb = MAXBLOCKS;

    cudaFuncSetAttribute(gcn_gumbel_mega,
                         cudaFuncAttributeMaxDynamicSharedMemorySize, SMEM_BYTES);

    gcn_wt_setup<<<(K * D / 4 + 255) / 256, 256>>>(Wg);
    gcn_gumbel_mega<<<nb, NTHREADS, SMEM_BYTES>>>(
        w, c, neg, gumbel, node_emb, ctx_emb, Wg,
        out, out_q, out_prior, B, 1.0f / (float)B);
}